// round 1
// baseline (speedup 1.0000x reference)
#include <cuda_runtime.h>

#define NN 100000
#define NE 1600000
#define DD 128

// ---------------- scratch (static __device__, allocation-free) ----------------
__device__ int   g_is64;
__device__ int   g_deg[NN];
__device__ int   g_rowptr[NN + 1];
__device__ int   g_cursor[NN];
__device__ int   g_src[NE];
__device__ float g_mean[(size_t)NN * DD];   // 51.2 MB
__device__ float g_h[(size_t)NN * DD];      // 51.2 MB

// ---------------- dtype detection (int64 vs silently-int32 edge_index) --------
// If the buffer really holds int64 node ids, every value is in [0, NN).
// If it holds int32 pairs read as int64, value = lo + (hi<<32) >= 2^32 unless
// hi==0 (prob ~1e-5 per entry) -> 64 clean entries ==> int64 for sure.
__global__ void k_detect(const void* ei) {
    const long long* p = (const long long*)ei;
    int ok64 = 1;
    for (int i = 0; i < 64; i++) {
        long long v = p[i];
        if (v < 0 || v >= NN) { ok64 = 0; break; }
    }
    g_is64 = ok64;
}

__device__ __forceinline__ int edge_src(const void* ei, int e) {
    return g_is64 ? (int)((const long long*)ei)[e] : ((const int*)ei)[e];
}
__device__ __forceinline__ int edge_dst(const void* ei, int e) {
    return g_is64 ? (int)((const long long*)ei)[(size_t)NE + e]
                  : ((const int*)ei)[(size_t)NE + e];
}

// ---------------- CSR build ----------------
__global__ void k_zero_deg() {
    int i = blockIdx.x * blockDim.x + threadIdx.x;
    if (i < NN) g_deg[i] = 0;
}

__global__ void k_degree(const void* ei) {
    int e = blockIdx.x * blockDim.x + threadIdx.x;
    if (e >= NE) return;
    atomicAdd(&g_deg[edge_dst(ei, e)], 1);
}

// single-block exclusive scan over NN degrees -> rowptr, cursor
__global__ void k_scan() {
    __shared__ int s[1024];
    const int CH = 98;                    // 1024*98 = 100352 >= NN
    int t = threadIdx.x;
    int start = t * CH;
    int end = start + CH; if (end > NN) end = NN;
    int sum = 0;
    for (int i = start; i < end; i++) sum += g_deg[i];
    s[t] = sum;
    __syncthreads();
    for (int off = 1; off < 1024; off <<= 1) {
        int v = (t >= off) ? s[t - off] : 0;
        __syncthreads();
        s[t] += v;
        __syncthreads();
    }
    int run = s[t] - sum;                 // exclusive prefix
    for (int i = start; i < end; i++) {
        g_rowptr[i] = run;
        g_cursor[i] = run;
        run += g_deg[i];
    }
    if (t == 1023) g_rowptr[NN] = s[1023];
}

__global__ void k_fill(const void* ei) {
    int e = blockIdx.x * blockDim.x + threadIdx.x;
    if (e >= NE) return;
    int s = edge_src(ei, e);
    int d = edge_dst(ei, e);
    int pos = atomicAdd(&g_cursor[d], 1);
    g_src[pos] = s;
}

// ---------------- mean aggregation: warp per node, lane owns a float4 ---------
__global__ void __launch_bounds__(256) k_agg(const float* __restrict__ in,
                                             float* __restrict__ outp) {
    int warp = (blockIdx.x * blockDim.x + threadIdx.x) >> 5;
    int lane = threadIdx.x & 31;
    if (warp >= NN) return;
    int beg = g_rowptr[warp];
    int end = g_rowptr[warp + 1];
    const float4* iv = (const float4*)in;
    float4 acc = make_float4(0.f, 0.f, 0.f, 0.f);
    int e = beg;
    for (; e + 4 <= end; e += 4) {
        int s0 = g_src[e], s1 = g_src[e + 1], s2 = g_src[e + 2], s3 = g_src[e + 3];
        float4 a = iv[s0 * 32 + lane];
        float4 b = iv[s1 * 32 + lane];
        float4 c = iv[s2 * 32 + lane];
        float4 d = iv[s3 * 32 + lane];
        acc.x += a.x + b.x + c.x + d.x;
        acc.y += a.y + b.y + c.y + d.y;
        acc.z += a.z + b.z + c.z + d.z;
        acc.w += a.w + b.w + c.w + d.w;
    }
    for (; e < end; e++) {
        float4 a = iv[g_src[e] * 32 + lane];
        acc.x += a.x; acc.y += a.y; acc.z += a.z; acc.w += a.w;
    }
    int deg = end - beg;
    float inv = 1.0f / (float)(deg > 0 ? deg : 1);
    float4 r = make_float4(acc.x * inv, acc.y * inv, acc.z * inv, acc.w * inv);
    ((float4*)outp)[warp * 32 + lane] = r;
}

// ---------------- fused dual-GEMM: out = mean@Wl + x@Wr + b (opt relu) --------
// Block: 256 threads; tile 64 nodes x 128 cols. tx (0..31) -> 4 cols (float4),
// ty (0..7) -> 8 consecutive nodes. Inputs staged in 64KB dynamic smem (LDS
// broadcast across tx), weights streamed from L2/L1 (128KB resident).
extern __shared__ float4 sbuf[];

__global__ void __launch_bounds__(256) k_linear(const float* __restrict__ mean,
                                                const float* __restrict__ xin,
                                                const float* __restrict__ Wl,
                                                const float* __restrict__ Wr,
                                                const float* __restrict__ bias,
                                                float* __restrict__ outp,
                                                int doRelu) {
    float4* sm = sbuf;            // [64][32] mean tile
    float4* sx = sbuf + 64 * 32;  // [64][32] x tile
    int tid = threadIdx.x;
    int node0 = blockIdx.x * 64;
    const float4* mv = (const float4*)mean;
    const float4* xv = (const float4*)xin;

    for (int t = tid; t < 64 * 32; t += 256) {
        int node = node0 + (t >> 5);
        float4 z = make_float4(0.f, 0.f, 0.f, 0.f);
        if (node < NN) {
            sm[t] = mv[node * 32 + (t & 31)];
            sx[t] = xv[node * 32 + (t & 31)];
        } else {
            sm[t] = z;
            sx[t] = z;
        }
    }
    __syncthreads();

    int tx = tid & 31;
    int ty = tid >> 5;
    int rbase = ty * 8;

    float4 acc[8];
#pragma unroll
    for (int i = 0; i < 8; i++) acc[i] = make_float4(0.f, 0.f, 0.f, 0.f);

    const float4* Wlv = (const float4*)Wl;   // [k][32 float4]
    const float4* Wrv = (const float4*)Wr;

    for (int k4 = 0; k4 < 32; k4++) {
        // ---- mean @ Wl ----
        float4 w0 = Wlv[(k4 * 4 + 0) * 32 + tx];
        float4 w1 = Wlv[(k4 * 4 + 1) * 32 + tx];
        float4 w2 = Wlv[(k4 * 4 + 2) * 32 + tx];
        float4 w3 = Wlv[(k4 * 4 + 3) * 32 + tx];
#pragma unroll
        for (int i = 0; i < 8; i++) {
            float4 m = sm[(rbase + i) * 32 + k4];
            acc[i].x += m.x * w0.x + m.y * w1.x + m.z * w2.x + m.w * w3.x;
            acc[i].y += m.x * w0.y + m.y * w1.y + m.z * w2.y + m.w * w3.y;
            acc[i].z += m.x * w0.z + m.y * w1.z + m.z * w2.z + m.w * w3.z;
            acc[i].w += m.x * w0.w + m.y * w1.w + m.z * w2.w + m.w * w3.w;
        }
        // ---- x @ Wr ----
        w0 = Wrv[(k4 * 4 + 0) * 32 + tx];
        w1 = Wrv[(k4 * 4 + 1) * 32 + tx];
        w2 = Wrv[(k4 * 4 + 2) * 32 + tx];
        w3 = Wrv[(k4 * 4 + 3) * 32 + tx];
#pragma unroll
        for (int i = 0; i < 8; i++) {
            float4 m = sx[(rbase + i) * 32 + k4];
            acc[i].x += m.x * w0.x + m.y * w1.x + m.z * w2.x + m.w * w3.x;
            acc[i].y += m.x * w0.y + m.y * w1.y + m.z * w2.y + m.w * w3.y;
            acc[i].z += m.x * w0.z + m.y * w1.z + m.z * w2.z + m.w * w3.z;
            acc[i].w += m.x * w0.w + m.y * w1.w + m.z * w2.w + m.w * w3.w;
        }
    }

    float4 bb = ((const float4*)bias)[tx];
#pragma unroll
    for (int i = 0; i < 8; i++) {
        int node = node0 + rbase + i;
        if (node < NN) {
            float4 r = make_float4(acc[i].x + bb.x, acc[i].y + bb.y,
                                   acc[i].z + bb.z, acc[i].w + bb.w);
            if (doRelu) {
                r.x = fmaxf(r.x, 0.f);
                r.y = fmaxf(r.y, 0.f);
                r.z = fmaxf(r.z, 0.f);
                r.w = fmaxf(r.w, 0.f);
            }
            ((float4*)outp)[node * 32 + tx] = r;
        }
    }
}

// ---------------- launch ----------------
extern "C" void kernel_launch(void* const* d_in, const int* in_sizes, int n_in,
                              void* d_out, int out_size) {
    const float* x   = (const float*)d_in[0];
    const void*  ei  = d_in[1];
    const float* Wl1 = (const float*)d_in[2];
    const float* Wr1 = (const float*)d_in[3];
    const float* b1  = (const float*)d_in[4];
    const float* Wl2 = (const float*)d_in[5];
    const float* Wr2 = (const float*)d_in[6];
    const float* b2  = (const float*)d_in[7];
    float* out = (float*)d_out;

    cudaFuncSetAttribute(k_linear, cudaFuncAttributeMaxDynamicSharedMemorySize,
                         65536);

    void *p_mean = nullptr, *p_h = nullptr;
    cudaGetSymbolAddress(&p_mean, g_mean);
    cudaGetSymbolAddress(&p_h, g_h);
    float* mean = (float*)p_mean;
    float* h    = (float*)p_h;

    // CSR build (per launch; deterministic)
    k_detect<<<1, 1>>>(ei);
    k_zero_deg<<<(NN + 255) / 256, 256>>>();
    k_degree<<<(NE + 255) / 256, 256>>>(ei);
    k_scan<<<1, 1024>>>();
    k_fill<<<(NE + 255) / 256, 256>>>(ei);

    // Layer 1
    k_agg<<<(NN + 7) / 8, 256>>>(x, mean);
    k_linear<<<(NN + 63) / 64, 256, 65536>>>(mean, x, Wl1, Wr1, b1, h, 1);

    // Layer 2
    k_agg<<<(NN + 7) / 8, 256>>>(h, mean);
    k_linear<<<(NN + 63) / 64, 256, 65536>>>(mean, h, Wl2, Wr2, b2, out, 0);
}

// round 3
// speedup vs baseline: 1.2952x; 1.2952x over previous
#include <cuda_runtime.h>

#define NN 100000
#define NE 1600000
#define DD 128
#define NBLK 391   // ceil(NN / 256)

// ---------------- scratch (static __device__, allocation-free) ----------------
__device__ int   g_is64;
__device__ int   g_deg[NN];
__device__ int   g_local[NN];
__device__ int   g_bsum[NBLK];
__device__ int   g_boff[NBLK];
__device__ int   g_rowptr[NN + 1];
__device__ int   g_cursor[NN];
__device__ int   g_src[NE];
__device__ float g_mean[(size_t)NN * DD];   // 51.2 MB
__device__ float g_h[(size_t)NN * DD];      // 51.2 MB

// ---------------- dtype detection (int64 vs silently-int32 edge_index) --------
// 32 parallel loads + ballot: one memory round-trip instead of a serial chain.
// int32 data misread as int64 gives v = lo + (hi<<32) >= 2^32 unless hi==0
// (p ~ 1e-5 per entry); all-32-clean is impossible in practice.
__global__ void k_detect(const void* ei) {
    int t = threadIdx.x;
    long long v = ((const long long*)ei)[t];
    unsigned bad = __ballot_sync(0xFFFFFFFFu, (v < 0) || (v >= NN));
    if (t == 0) g_is64 = (bad == 0) ? 1 : 0;
}

__device__ __forceinline__ int edge_src(const void* ei, int e) {
    return g_is64 ? (int)((const long long*)ei)[e] : ((const int*)ei)[e];
}
__device__ __forceinline__ int edge_dst(const void* ei, int e) {
    return g_is64 ? (int)((const long long*)ei)[(size_t)NE + e]
                  : ((const int*)ei)[(size_t)NE + e];
}

// ---------------- CSR build ----------------
__global__ void k_zero_deg() {
    int i = blockIdx.x * blockDim.x + threadIdx.x;
    if (i < NN) g_deg[i] = 0;
}

__global__ void k_degree(const void* ei) {
    int e = blockIdx.x * blockDim.x + threadIdx.x;
    if (e >= NE) return;
    atomicAdd(&g_deg[edge_dst(ei, e)], 1);
}

// --- 3-phase parallel exclusive scan over degrees ---
// Phase 1: per-block (256-wide) inclusive scan via shuffles; write local
// exclusive prefix + per-block total.
__global__ void __launch_bounds__(256) k_scan1() {
    __shared__ int ws[8];
    int b = blockIdx.x, t = threadIdx.x;
    int i = b * 256 + t;
    int v = (i < NN) ? g_deg[i] : 0;
    int x = v;
#pragma unroll
    for (int o = 1; o < 32; o <<= 1) {
        int y = __shfl_up_sync(0xFFFFFFFFu, x, o);
        if ((t & 31) >= o) x += y;
    }
    if ((t & 31) == 31) ws[t >> 5] = x;
    __syncthreads();
    if (t < 8) {
        int y = ws[t];
#pragma unroll
        for (int o = 1; o < 8; o <<= 1) {
            int z = __shfl_up_sync(0x000000FFu, y, o);
            if (t >= o) y += z;
        }
        ws[t] = y;
    }
    __syncthreads();
    int incl = x + ((t >= 32) ? ws[(t >> 5) - 1] : 0);
    if (i < NN) g_local[i] = incl - v;
    if (t == 255) g_bsum[b] = incl;
}

// Phase 2: single block scans the 391 block sums (512 threads, 16 warps).
__global__ void __launch_bounds__(512) k_scan2() {
    __shared__ int ws[16];
    int t = threadIdx.x;
    int v = (t < NBLK) ? g_bsum[t] : 0;
    int x = v;
#pragma unroll
    for (int o = 1; o < 32; o <<= 1) {
        int y = __shfl_up_sync(0xFFFFFFFFu, x, o);
        if ((t & 31) >= o) x += y;
    }
    if ((t & 31) == 31) ws[t >> 5] = x;
    __syncthreads();
    if (t < 16) {
        int y = ws[t];
#pragma unroll
        for (int o = 1; o < 16; o <<= 1) {
            int z = __shfl_up_sync(0x0000FFFFu, y, o);
            if (t >= o) y += z;
        }
        ws[t] = y;
    }
    __syncthreads();
    int incl = x + ((t >= 32) ? ws[(t >> 5) - 1] : 0);
    if (t < NBLK) g_boff[t] = incl - v;
    if (t == NBLK - 1) g_rowptr[NN] = incl;   // grand total (= NE)
}

// Phase 3: expand to rowptr/cursor.
__global__ void k_scan3() {
    int i = blockIdx.x * blockDim.x + threadIdx.x;
    if (i >= NN) return;
    int r = g_boff[i >> 8] + g_local[i];
    g_rowptr[i] = r;
    g_cursor[i] = r;
}

__global__ void k_fill(const void* ei) {
    int e = blockIdx.x * blockDim.x + threadIdx.x;
    if (e >= NE) return;
    int s = edge_src(ei, e);
    int d = edge_dst(ei, e);
    int pos = atomicAdd(&g_cursor[d], 1);
    g_src[pos] = s;
}

// ---------------- mean aggregation: warp per node, lane owns a float4 ---------
__global__ void __launch_bounds__(256) k_agg(const float* __restrict__ in,
                                             float* __restrict__ outp) {
    int warp = (blockIdx.x * blockDim.x + threadIdx.x) >> 5;
    int lane = threadIdx.x & 31;
    if (warp >= NN) return;
    int beg = g_rowptr[warp];
    int end = g_rowptr[warp + 1];
    const float4* iv = (const float4*)in;
    float4 acc = make_float4(0.f, 0.f, 0.f, 0.f);
    int e = beg;
    for (; e + 4 <= end; e += 4) {
        int s0 = g_src[e], s1 = g_src[e + 1], s2 = g_src[e + 2], s3 = g_src[e + 3];
        float4 a = iv[s0 * 32 + lane];
        float4 b = iv[s1 * 32 + lane];
        float4 c = iv[s2 * 32 + lane];
        float4 d = iv[s3 * 32 + lane];
        acc.x += a.x + b.x + c.x + d.x;
        acc.y += a.y + b.y + c.y + d.y;
        acc.z += a.z + b.z + c.z + d.z;
        acc.w += a.w + b.w + c.w + d.w;
    }
    for (; e < end; e++) {
        float4 a = iv[g_src[e] * 32 + lane];
        acc.x += a.x; acc.y += a.y; acc.z += a.z; acc.w += a.w;
    }
    int deg = end - beg;
    float inv = 1.0f / (float)(deg > 0 ? deg : 1);
    float4 r = make_float4(acc.x * inv, acc.y * inv, acc.z * inv, acc.w * inv);
    ((float4*)outp)[warp * 32 + lane] = r;
}

// ---------------- fused dual-GEMM: out = mean@Wl + x@Wr + b (opt relu) --------
extern __shared__ float4 sbuf[];

__global__ void __launch_bounds__(256) k_linear(const float* __restrict__ mean,
                                                const float* __restrict__ xin,
                                                const float* __restrict__ Wl,
                                                const float* __restrict__ Wr,
                                                const float* __restrict__ bias,
                                                float* __restrict__ outp,
                                                int doRelu) {
    float4* sm = sbuf;            // [64][32] mean tile
    float4* sx = sbuf + 64 * 32;  // [64][32] x tile
    int tid = threadIdx.x;
    int node0 = blockIdx.x * 64;
    const float4* mv = (const float4*)mean;
    const float4* xv = (const float4*)xin;

    for (int t = tid; t < 64 * 32; t += 256) {
        int node = node0 + (t >> 5);
        float4 z = make_float4(0.f, 0.f, 0.f, 0.f);
        if (node < NN) {
            sm[t] = mv[node * 32 + (t & 31)];
            sx[t] = xv[node * 32 + (t & 31)];
        } else {
            sm[t] = z;
            sx[t] = z;
        }
    }
    __syncthreads();

    int tx = tid & 31;
    int ty = tid >> 5;
    int rbase = ty * 8;

    float4 acc[8];
#pragma unroll
    for (int i = 0; i < 8; i++) acc[i] = make_float4(0.f, 0.f, 0.f, 0.f);

    const float4* Wlv = (const float4*)Wl;   // [k][32 float4]
    const float4* Wrv = (const float4*)Wr;

    for (int k4 = 0; k4 < 32; k4++) {
        float4 w0 = Wlv[(k4 * 4 + 0) * 32 + tx];
        float4 w1 = Wlv[(k4 * 4 + 1) * 32 + tx];
        float4 w2 = Wlv[(k4 * 4 + 2) * 32 + tx];
        float4 w3 = Wlv[(k4 * 4 + 3) * 32 + tx];
#pragma unroll
        for (int i = 0; i < 8; i++) {
            float4 m = sm[(rbase + i) * 32 + k4];
            acc[i].x += m.x * w0.x + m.y * w1.x + m.z * w2.x + m.w * w3.x;
            acc[i].y += m.x * w0.y + m.y * w1.y + m.z * w2.y + m.w * w3.y;
            acc[i].z += m.x * w0.z + m.y * w1.z + m.z * w2.z + m.w * w3.z;
            acc[i].w += m.x * w0.w + m.y * w1.w + m.z * w2.w + m.w * w3.w;
        }
        w0 = Wrv[(k4 * 4 + 0) * 32 + tx];
        w1 = Wrv[(k4 * 4 + 1) * 32 + tx];
        w2 = Wrv[(k4 * 4 + 2) * 32 + tx];
        w3 = Wrv[(k4 * 4 + 3) * 32 + tx];
#pragma unroll
        for (int i = 0; i < 8; i++) {
            float4 m = sx[(rbase + i) * 32 + k4];
            acc[i].x += m.x * w0.x + m.y * w1.x + m.z * w2.x + m.w * w3.x;
            acc[i].y += m.x * w0.y + m.y * w1.y + m.z * w2.y + m.w * w3.y;
            acc[i].z += m.x * w0.z + m.y * w1.z + m.z * w2.z + m.w * w3.z;
            acc[i].w += m.x * w0.w + m.y * w1.w + m.z * w2.w + m.w * w3.w;
        }
    }

    float4 bb = ((const float4*)bias)[tx];
#pragma unroll
    for (int i = 0; i < 8; i++) {
        int node = node0 + rbase + i;
        if (node < NN) {
            float4 r = make_float4(acc[i].x + bb.x, acc[i].y + bb.y,
                                   acc[i].z + bb.z, acc[i].w + bb.w);
            if (doRelu) {
                r.x = fmaxf(r.x, 0.f);
                r.y = fmaxf(r.y, 0.f);
                r.z = fmaxf(r.z, 0.f);
                r.w = fmaxf(r.w, 0.f);
            }
            ((float4*)outp)[node * 32 + tx] = r;
        }
    }
}

// ---------------- launch ----------------
extern "C" void kernel_launch(void* const* d_in, const int* in_sizes, int n_in,
                              void* d_out, int out_size) {
    const float* x   = (const float*)d_in[0];
    const void*  ei  = d_in[1];
    const float* Wl1 = (const float*)d_in[2];
    const float* Wr1 = (const float*)d_in[3];
    const float* b1  = (const float*)d_in[4];
    const float* Wl2 = (const float*)d_in[5];
    const float* Wr2 = (const float*)d_in[6];
    const float* b2  = (const float*)d_in[7];
    float* out = (float*)d_out;

    cudaFuncSetAttribute(k_linear, cudaFuncAttributeMaxDynamicSharedMemorySize,
                         65536);

    void *p_mean = nullptr, *p_h = nullptr;
    cudaGetSymbolAddress(&p_mean, g_mean);
    cudaGetSymbolAddress(&p_h, g_h);
    float* mean = (float*)p_mean;
    float* h    = (float*)p_h;

    // CSR build (per launch; deterministic)
    k_detect<<<1, 32>>>(ei);
    k_zero_deg<<<(NN + 255) / 256, 256>>>();
    k_degree<<<(NE + 255) / 256, 256>>>(ei);
    k_scan1<<<NBLK, 256>>>();
    k_scan2<<<1, 512>>>();
    k_scan3<<<(NN + 255) / 256, 256>>>();
    k_fill<<<(NE + 255) / 256, 256>>>(ei);

    // Layer 1
    k_agg<<<(NN + 7) / 8, 256>>>(x, mean);
    k_linear<<<(NN + 63) / 64, 256, 65536>>>(mean, x, Wl1, Wr1, b1, h, 1);

    // Layer 2
    k_agg<<<(NN + 7) / 8, 256>>>(h, mean);
    k_linear<<<(NN + 63) / 64, 256, 65536>>>(mean, h, Wl2, Wr2, b2, out, 0);
}

// round 4
// speedup vs baseline: 1.4202x; 1.0965x over previous
#include <cuda_runtime.h>

#define NN 100000
#define NE 1600000
#define DD 128
#define NBLK 391   // ceil(NN / 256)

// ---------------- scratch (static __device__, allocation-free) ----------------
__device__ int   g_is64;
__device__ int   g_deg[NN];
__device__ int   g_local[NN];
__device__ int   g_bsum[NBLK];
__device__ int   g_boff[NBLK];
__device__ int   g_rowptr[NN + 1];
__device__ int   g_cursor[NN];
__device__ int   g_src[NE];
__device__ float g_mean[(size_t)NN * DD];   // 51.2 MB
__device__ float g_h[(size_t)NN * DD];      // 51.2 MB

// ---------------- packed f32x2 helpers (Blackwell FFMA2 path) ----------------
__device__ __forceinline__ unsigned long long pk2(float lo, float hi) {
    unsigned long long r;
    asm("mov.b64 %0, {%1, %2};" : "=l"(r) : "f"(lo), "f"(hi));
    return r;
}
__device__ __forceinline__ void upk2(unsigned long long v, float& lo, float& hi) {
    asm("mov.b64 {%0, %1}, %2;" : "=f"(lo), "=f"(hi) : "l"(v));
}
__device__ __forceinline__ void ffma2(unsigned long long& d,
                                      unsigned long long a,
                                      unsigned long long b) {
    asm("fma.rn.f32x2 %0, %1, %2, %0;" : "+l"(d) : "l"(a), "l"(b));
}

// ---------------- dtype detection (int64 vs silently-int32 edge_index) --------
__global__ void k_detect(const void* ei) {
    int t = threadIdx.x;
    long long v = ((const long long*)ei)[t];
    unsigned bad = __ballot_sync(0xFFFFFFFFu, (v < 0) || (v >= NN));
    if (t == 0) g_is64 = (bad == 0) ? 1 : 0;
}

__device__ __forceinline__ int edge_src(const void* ei, int e) {
    return g_is64 ? (int)((const long long*)ei)[e] : ((const int*)ei)[e];
}
__device__ __forceinline__ int edge_dst(const void* ei, int e) {
    return g_is64 ? (int)((const long long*)ei)[(size_t)NE + e]
                  : ((const int*)ei)[(size_t)NE + e];
}

// ---------------- CSR build ----------------
__global__ void k_zero_deg() {
    int i = blockIdx.x * blockDim.x + threadIdx.x;
    if (i < NN) g_deg[i] = 0;
}

__global__ void k_degree(const void* ei) {
    int e = blockIdx.x * blockDim.x + threadIdx.x;
    if (e >= NE) return;
    atomicAdd(&g_deg[edge_dst(ei, e)], 1);
}

// Phase 1: per-block inclusive scan via shuffles.
__global__ void __launch_bounds__(256) k_scan1() {
    __shared__ int ws[8];
    int b = blockIdx.x, t = threadIdx.x;
    int i = b * 256 + t;
    int v = (i < NN) ? g_deg[i] : 0;
    int x = v;
#pragma unroll
    for (int o = 1; o < 32; o <<= 1) {
        int y = __shfl_up_sync(0xFFFFFFFFu, x, o);
        if ((t & 31) >= o) x += y;
    }
    if ((t & 31) == 31) ws[t >> 5] = x;
    __syncthreads();
    if (t < 8) {
        int y = ws[t];
#pragma unroll
        for (int o = 1; o < 8; o <<= 1) {
            int z = __shfl_up_sync(0x000000FFu, y, o);
            if (t >= o) y += z;
        }
        ws[t] = y;
    }
    __syncthreads();
    int incl = x + ((t >= 32) ? ws[(t >> 5) - 1] : 0);
    if (i < NN) g_local[i] = incl - v;
    if (t == 255) g_bsum[b] = incl;
}

// Phase 2: single block scans the 391 block sums.
__global__ void __launch_bounds__(512) k_scan2() {
    __shared__ int ws[16];
    int t = threadIdx.x;
    int v = (t < NBLK) ? g_bsum[t] : 0;
    int x = v;
#pragma unroll
    for (int o = 1; o < 32; o <<= 1) {
        int y = __shfl_up_sync(0xFFFFFFFFu, x, o);
        if ((t & 31) >= o) x += y;
    }
    if ((t & 31) == 31) ws[t >> 5] = x;
    __syncthreads();
    if (t < 16) {
        int y = ws[t];
#pragma unroll
        for (int o = 1; o < 16; o <<= 1) {
            int z = __shfl_up_sync(0x0000FFFFu, y, o);
            if (t >= o) y += z;
        }
        ws[t] = y;
    }
    __syncthreads();
    int incl = x + ((t >= 32) ? ws[(t >> 5) - 1] : 0);
    if (t < NBLK) g_boff[t] = incl - v;
    if (t == NBLK - 1) g_rowptr[NN] = incl;
}

// Phase 3: expand to rowptr/cursor.
__global__ void k_scan3() {
    int i = blockIdx.x * blockDim.x + threadIdx.x;
    if (i >= NN) return;
    int r = g_boff[i >> 8] + g_local[i];
    g_rowptr[i] = r;
    g_cursor[i] = r;
}

__global__ void k_fill(const void* ei) {
    int e = blockIdx.x * blockDim.x + threadIdx.x;
    if (e >= NE) return;
    int s = edge_src(ei, e);
    int d = edge_dst(ei, e);
    int pos = atomicAdd(&g_cursor[d], 1);
    g_src[pos] = s;
}

// ---------------- mean aggregation: warp per node, lane owns a float4 ---------
// 8-edge unroll, two independent accumulator chains for MLP.
__global__ void __launch_bounds__(256) k_agg(const float* __restrict__ in,
                                             float* __restrict__ outp) {
    int warp = (blockIdx.x * blockDim.x + threadIdx.x) >> 5;
    int lane = threadIdx.x & 31;
    if (warp >= NN) return;
    int beg = g_rowptr[warp];
    int end = g_rowptr[warp + 1];
    const float4* iv = (const float4*)in;
    float4 acc0 = make_float4(0.f, 0.f, 0.f, 0.f);
    float4 acc1 = make_float4(0.f, 0.f, 0.f, 0.f);
    int e = beg;
    for (; e + 8 <= end; e += 8) {
        int s0 = g_src[e],     s1 = g_src[e + 1], s2 = g_src[e + 2], s3 = g_src[e + 3];
        int s4 = g_src[e + 4], s5 = g_src[e + 5], s6 = g_src[e + 6], s7 = g_src[e + 7];
        float4 a = iv[s0 * 32 + lane];
        float4 b = iv[s1 * 32 + lane];
        float4 c = iv[s2 * 32 + lane];
        float4 d = iv[s3 * 32 + lane];
        float4 p = iv[s4 * 32 + lane];
        float4 q = iv[s5 * 32 + lane];
        float4 r = iv[s6 * 32 + lane];
        float4 s = iv[s7 * 32 + lane];
        acc0.x += a.x + b.x + c.x + d.x;
        acc0.y += a.y + b.y + c.y + d.y;
        acc0.z += a.z + b.z + c.z + d.z;
        acc0.w += a.w + b.w + c.w + d.w;
        acc1.x += p.x + q.x + r.x + s.x;
        acc1.y += p.y + q.y + r.y + s.y;
        acc1.z += p.z + q.z + r.z + s.z;
        acc1.w += p.w + q.w + r.w + s.w;
    }
    for (; e < end; e++) {
        float4 a = iv[g_src[e] * 32 + lane];
        acc0.x += a.x; acc0.y += a.y; acc0.z += a.z; acc0.w += a.w;
    }
    int deg = end - beg;
    float inv = 1.0f / (float)(deg > 0 ? deg : 1);
    float4 r = make_float4((acc0.x + acc1.x) * inv, (acc0.y + acc1.y) * inv,
                           (acc0.z + acc1.z) * inv, (acc0.w + acc1.w) * inv);
    ((float4*)outp)[warp * 32 + lane] = r;
}

// ---------------- fused dual-GEMM: out = mean@Wl + x@Wr + b (opt relu) --------
// Mainloop rewritten with fma.rn.f32x2 (FFMA2) -> 2x fp32 pipe throughput.
// Accumulators packed over column pairs (x,y) and (z,w); weight pairs are
// register-aligned halves of the float4 LDG; m-broadcast packs go to alu pipe.
extern __shared__ float4 sbuf[];

__global__ void __launch_bounds__(256) k_linear(const float* __restrict__ mean,
                                                const float* __restrict__ xin,
                                                const float* __restrict__ Wl,
                                                const float* __restrict__ Wr,
                                                const float* __restrict__ bias,
                                                float* __restrict__ outp,
                                                int doRelu) {
    float4* sm = sbuf;            // [64][32] mean tile
    float4* sx = sbuf + 64 * 32;  // [64][32] x tile
    int tid = threadIdx.x;
    int node0 = blockIdx.x * 64;
    const float4* mv = (const float4*)mean;
    const float4* xv = (const float4*)xin;

    for (int t = tid; t < 64 * 32; t += 256) {
        int node = node0 + (t >> 5);
        float4 z = make_float4(0.f, 0.f, 0.f, 0.f);
        if (node < NN) {
            sm[t] = mv[node * 32 + (t & 31)];
            sx[t] = xv[node * 32 + (t & 31)];
        } else {
            sm[t] = z;
            sx[t] = z;
        }
    }
    __syncthreads();

    int tx = tid & 31;
    int ty = tid >> 5;
    int rbase = ty * 8;

    unsigned long long axy[8], azw[8];
#pragma unroll
    for (int i = 0; i < 8; i++) { axy[i] = 0ull; azw[i] = 0ull; }

    const float4* Wlv = (const float4*)Wl;   // [k][32 float4]
    const float4* Wrv = (const float4*)Wr;

    for (int k4 = 0; k4 < 32; k4++) {
        // ---- mean @ Wl ----
        {
            float4 w0 = Wlv[(k4 * 4 + 0) * 32 + tx];
            float4 w1 = Wlv[(k4 * 4 + 1) * 32 + tx];
            float4 w2 = Wlv[(k4 * 4 + 2) * 32 + tx];
            float4 w3 = Wlv[(k4 * 4 + 3) * 32 + tx];
            unsigned long long w0xy = pk2(w0.x, w0.y), w0zw = pk2(w0.z, w0.w);
            unsigned long long w1xy = pk2(w1.x, w1.y), w1zw = pk2(w1.z, w1.w);
            unsigned long long w2xy = pk2(w2.x, w2.y), w2zw = pk2(w2.z, w2.w);
            unsigned long long w3xy = pk2(w3.x, w3.y), w3zw = pk2(w3.z, w3.w);
#pragma unroll
            for (int i = 0; i < 8; i++) {
                float4 m = sm[(rbase + i) * 32 + k4];
                unsigned long long mm;
                mm = pk2(m.x, m.x); ffma2(axy[i], mm, w0xy); ffma2(azw[i], mm, w0zw);
                mm = pk2(m.y, m.y); ffma2(axy[i], mm, w1xy); ffma2(azw[i], mm, w1zw);
                mm = pk2(m.z, m.z); ffma2(axy[i], mm, w2xy); ffma2(azw[i], mm, w2zw);
                mm = pk2(m.w, m.w); ffma2(axy[i], mm, w3xy); ffma2(azw[i], mm, w3zw);
            }
        }
        // ---- x @ Wr ----
        {
            float4 w0 = Wrv[(k4 * 4 + 0) * 32 + tx];
            float4 w1 = Wrv[(k4 * 4 + 1) * 32 + tx];
            float4 w2 = Wrv[(k4 * 4 + 2) * 32 + tx];
            float4 w3 = Wrv[(k4 * 4 + 3) * 32 + tx];
            unsigned long long w0xy = pk2(w0.x, w0.y), w0zw = pk2(w0.z, w0.w);
            unsigned long long w1xy = pk2(w1.x, w1.y), w1zw = pk2(w1.z, w1.w);
            unsigned long long w2xy = pk2(w2.x, w2.y), w2zw = pk2(w2.z, w2.w);
            unsigned long long w3xy = pk2(w3.x, w3.y), w3zw = pk2(w3.z, w3.w);
#pragma unroll
            for (int i = 0; i < 8; i++) {
                float4 m = sx[(rbase + i) * 32 + k4];
                unsigned long long mm;
                mm = pk2(m.x, m.x); ffma2(axy[i], mm, w0xy); ffma2(azw[i], mm, w0zw);
                mm = pk2(m.y, m.y); ffma2(axy[i], mm, w1xy); ffma2(azw[i], mm, w1zw);
                mm = pk2(m.z, m.z); ffma2(axy[i], mm, w2xy); ffma2(azw[i], mm, w2zw);
                mm = pk2(m.w, m.w); ffma2(axy[i], mm, w3xy); ffma2(azw[i], mm, w3zw);
            }
        }
    }

    float4 bb = ((const float4*)bias)[tx];
#pragma unroll
    for (int i = 0; i < 8; i++) {
        int node = node0 + rbase + i;
        if (node < NN) {
            float4 r;
            upk2(axy[i], r.x, r.y);
            upk2(azw[i], r.z, r.w);
            r.x += bb.x; r.y += bb.y; r.z += bb.z; r.w += bb.w;
            if (doRelu) {
                r.x = fmaxf(r.x, 0.f);
                r.y = fmaxf(r.y, 0.f);
                r.z = fmaxf(r.z, 0.f);
                r.w = fmaxf(r.w, 0.f);
            }
            ((float4*)outp)[node * 32 + tx] = r;
        }
    }
}

// ---------------- launch ----------------
extern "C" void kernel_launch(void* const* d_in, const int* in_sizes, int n_in,
                              void* d_out, int out_size) {
    const float* x   = (const float*)d_in[0];
    const void*  ei  = d_in[1];
    const float* Wl1 = (const float*)d_in[2];
    const float* Wr1 = (const float*)d_in[3];
    const float* b1  = (const float*)d_in[4];
    const float* Wl2 = (const float*)d_in[5];
    const float* Wr2 = (const float*)d_in[6];
    const float* b2  = (const float*)d_in[7];
    float* out = (float*)d_out;

    cudaFuncSetAttribute(k_linear, cudaFuncAttributeMaxDynamicSharedMemorySize,
                         65536);

    void *p_mean = nullptr, *p_h = nullptr;
    cudaGetSymbolAddress(&p_mean, g_mean);
    cudaGetSymbolAddress(&p_h, g_h);
    float* mean = (float*)p_mean;
    float* h    = (float*)p_h;

    // CSR build (per launch; deterministic up to fp32 summation order)
    k_detect<<<1, 32>>>(ei);
    k_zero_deg<<<(NN + 255) / 256, 256>>>();
    k_degree<<<(NE + 255) / 256, 256>>>(ei);
    k_scan1<<<NBLK, 256>>>();
    k_scan2<<<1, 512>>>();
    k_scan3<<<(NN + 255) / 256, 256>>>();
    k_fill<<<(NE + 255) / 256, 256>>>(ei);

    // Layer 1
    k_agg<<<(NN + 7) / 8, 256>>>(x, mean);
    k_linear<<<(NN + 63) / 64, 256, 65536>>>(mean, x, Wl1, Wr1, b1, h, 1);

    // Layer 2
    k_agg<<<(NN + 7) / 8, 256>>>(h, mean);
    k_linear<<<(NN + 63) / 64, 256, 65536>>>(mean, h, Wl2, Wr2, b2, out, 0);
}

// round 5
// speedup vs baseline: 1.4262x; 1.0042x over previous
#include <cuda_runtime.h>
#include <cuda_fp16.h>

#define NN 100000
#define NE 1600000
#define DD 128
#define NBLK 391   // ceil(NN / 256)

// ---------------- scratch (static __device__, allocation-free) ----------------
__device__ int    g_is64;
__device__ int    g_deg[NN];
__device__ int    g_local[NN];
__device__ int    g_bsum[NBLK];
__device__ int    g_boff[NBLK];
__device__ int    g_rowptr[NN + 1];
__device__ int    g_cursor[NN];
__device__ int    g_src[NE];
__device__ float  g_mean[(size_t)NN * DD];    // 51.2 MB
__device__ float  g_h[(size_t)NN * DD];       // 51.2 MB
__device__ __half g_xh[(size_t)NN * DD];      // 25.6 MB fp16 gather cache (x)
__device__ __half g_hh[(size_t)NN * DD];      // 25.6 MB fp16 gather cache (h)

// ---------------- packed f32x2 helpers (Blackwell FFMA2 path) ----------------
__device__ __forceinline__ unsigned long long pk2(float lo, float hi) {
    unsigned long long r;
    asm("mov.b64 %0, {%1, %2};" : "=l"(r) : "f"(lo), "f"(hi));
    return r;
}
__device__ __forceinline__ void upk2(unsigned long long v, float& lo, float& hi) {
    asm("mov.b64 {%0, %1}, %2;" : "=f"(lo), "=f"(hi) : "l"(v));
}
__device__ __forceinline__ void ffma2(unsigned long long& d,
                                      unsigned long long a,
                                      unsigned long long b) {
    asm("fma.rn.f32x2 %0, %1, %2, %0;" : "+l"(d) : "l"(a), "l"(b));
}

// ---------------- dtype detection (int64 vs silently-int32 edge_index) --------
__global__ void k_detect(const void* ei) {
    int t = threadIdx.x;
    long long v = ((const long long*)ei)[t];
    unsigned bad = __ballot_sync(0xFFFFFFFFu, (v < 0) || (v >= NN));
    if (t == 0) g_is64 = (bad == 0) ? 1 : 0;
}

__device__ __forceinline__ int edge_src(const void* ei, int e) {
    return g_is64 ? (int)((const long long*)ei)[e] : ((const int*)ei)[e];
}
__device__ __forceinline__ int edge_dst(const void* ei, int e) {
    return g_is64 ? (int)((const long long*)ei)[(size_t)NE + e]
                  : ((const int*)ei)[(size_t)NE + e];
}

// ---------------- fp32 -> fp16 cache conversion (4 elems / thread) ----------
__global__ void __launch_bounds__(256) k_tohalf(const float* __restrict__ in,
                                                __half* __restrict__ outp) {
    int i = blockIdx.x * blockDim.x + threadIdx.x;   // float4 index
    if (i >= NN * DD / 4) return;
    float4 v = ((const float4*)in)[i];
    __half2 a = __floats2half2_rn(v.x, v.y);
    __half2 b = __floats2half2_rn(v.z, v.w);
    uint2 u;
    u.x = *reinterpret_cast<unsigned*>(&a);
    u.y = *reinterpret_cast<unsigned*>(&b);
    ((uint2*)outp)[i] = u;
}

// ---------------- CSR build ----------------
__global__ void k_zero_deg() {
    int i = blockIdx.x * blockDim.x + threadIdx.x;
    if (i < NN) g_deg[i] = 0;
}

__global__ void k_degree(const void* ei) {
    int e = blockIdx.x * blockDim.x + threadIdx.x;
    if (e >= NE) return;
    atomicAdd(&g_deg[edge_dst(ei, e)], 1);
}

// Phase 1: per-block inclusive scan via shuffles.
__global__ void __launch_bounds__(256) k_scan1() {
    __shared__ int ws[8];
    int b = blockIdx.x, t = threadIdx.x;
    int i = b * 256 + t;
    int v = (i < NN) ? g_deg[i] : 0;
    int x = v;
#pragma unroll
    for (int o = 1; o < 32; o <<= 1) {
        int y = __shfl_up_sync(0xFFFFFFFFu, x, o);
        if ((t & 31) >= o) x += y;
    }
    if ((t & 31) == 31) ws[t >> 5] = x;
    __syncthreads();
    if (t < 8) {
        int y = ws[t];
#pragma unroll
        for (int o = 1; o < 8; o <<= 1) {
            int z = __shfl_up_sync(0x000000FFu, y, o);
            if (t >= o) y += z;
        }
        ws[t] = y;
    }
    __syncthreads();
    int incl = x + ((t >= 32) ? ws[(t >> 5) - 1] : 0);
    if (i < NN) g_local[i] = incl - v;
    if (t == 255) g_bsum[b] = incl;
}

// Phase 2: single block scans the 391 block sums.
__global__ void __launch_bounds__(512) k_scan2() {
    __shared__ int ws[16];
    int t = threadIdx.x;
    int v = (t < NBLK) ? g_bsum[t] : 0;
    int x = v;
#pragma unroll
    for (int o = 1; o < 32; o <<= 1) {
        int y = __shfl_up_sync(0xFFFFFFFFu, x, o);
        if ((t & 31) >= o) x += y;
    }
    if ((t & 31) == 31) ws[t >> 5] = x;
    __syncthreads();
    if (t < 16) {
        int y = ws[t];
#pragma unroll
        for (int o = 1; o < 16; o <<= 1) {
            int z = __shfl_up_sync(0x0000FFFFu, y, o);
            if (t >= o) y += z;
        }
        ws[t] = y;
    }
    __syncthreads();
    int incl = x + ((t >= 32) ? ws[(t >> 5) - 1] : 0);
    if (t < NBLK) g_boff[t] = incl - v;
    if (t == NBLK - 1) g_rowptr[NN] = incl;
}

// Phase 3: expand to rowptr/cursor.
__global__ void k_scan3() {
    int i = blockIdx.x * blockDim.x + threadIdx.x;
    if (i >= NN) return;
    int r = g_boff[i >> 8] + g_local[i];
    g_rowptr[i] = r;
    g_cursor[i] = r;
}

__global__ void k_fill(const void* ei) {
    int e = blockIdx.x * blockDim.x + threadIdx.x;
    if (e >= NE) return;
    int s = edge_src(ei, e);
    int d = edge_dst(ei, e);
    int pos = atomicAdd(&g_cursor[d], 1);
    g_src[pos] = s;
}

// ---------------- mean aggregation over fp16 cache ---------------------------
// Warp per node; lane owns 4 features (one uint2 = 2x half2 = 8B). Row = 256B.
// Accumulate in fp32; 8-edge unroll, two accumulator chains.
__global__ void __launch_bounds__(256) k_agg(const __half* __restrict__ in,
                                             float* __restrict__ outp) {
    int warp = (blockIdx.x * blockDim.x + threadIdx.x) >> 5;
    int lane = threadIdx.x & 31;
    if (warp >= NN) return;
    int beg = g_rowptr[warp];
    int end = g_rowptr[warp + 1];
    const uint2* iv = (const uint2*)in;
    float4 acc0 = make_float4(0.f, 0.f, 0.f, 0.f);
    float4 acc1 = make_float4(0.f, 0.f, 0.f, 0.f);

    int e = beg;
    for (; e + 8 <= end; e += 8) {
        int s0 = g_src[e],     s1 = g_src[e + 1], s2 = g_src[e + 2], s3 = g_src[e + 3];
        int s4 = g_src[e + 4], s5 = g_src[e + 5], s6 = g_src[e + 6], s7 = g_src[e + 7];
        uint2 u0 = iv[s0 * 32 + lane];
        uint2 u1 = iv[s1 * 32 + lane];
        uint2 u2 = iv[s2 * 32 + lane];
        uint2 u3 = iv[s3 * 32 + lane];
        uint2 u4 = iv[s4 * 32 + lane];
        uint2 u5 = iv[s5 * 32 + lane];
        uint2 u6 = iv[s6 * 32 + lane];
        uint2 u7 = iv[s7 * 32 + lane];
#define ACCUM(ACC, U)                                                         \
        {                                                                     \
            float2 lo = __half22float2(*reinterpret_cast<__half2*>(&(U).x));  \
            float2 hi = __half22float2(*reinterpret_cast<__half2*>(&(U).y));  \
            ACC.x += lo.x; ACC.y += lo.y; ACC.z += hi.x; ACC.w += hi.y;       \
        }
        ACCUM(acc0, u0) ACCUM(acc0, u1) ACCUM(acc0, u2) ACCUM(acc0, u3)
        ACCUM(acc1, u4) ACCUM(acc1, u5) ACCUM(acc1, u6) ACCUM(acc1, u7)
    }
    for (; e < end; e++) {
        uint2 u = iv[g_src[e] * 32 + lane];
        ACCUM(acc0, u)
    }
#undef ACCUM
    int deg = end - beg;
    float inv = 1.0f / (float)(deg > 0 ? deg : 1);
    float4 r = make_float4((acc0.x + acc1.x) * inv, (acc0.y + acc1.y) * inv,
                           (acc0.z + acc1.z) * inv, (acc0.w + acc1.w) * inv);
    ((float4*)outp)[warp * 32 + lane] = r;
}

// ---------------- fused dual-GEMM: out = mean@Wl + x@Wr + b (opt relu) --------
// FFMA2 mainloop. Optional fp16 shadow write of the output (gather cache for
// the next layer).
extern __shared__ float4 sbuf[];

__global__ void __launch_bounds__(256) k_linear(const float* __restrict__ mean,
                                                const float* __restrict__ xin,
                                                const float* __restrict__ Wl,
                                                const float* __restrict__ Wr,
                                                const float* __restrict__ bias,
                                                float* __restrict__ outp,
                                                __half* __restrict__ outh,
                                                int doRelu) {
    float4* sm = sbuf;            // [64][32] mean tile
    float4* sx = sbuf + 64 * 32;  // [64][32] x tile
    int tid = threadIdx.x;
    int node0 = blockIdx.x * 64;
    const float4* mv = (const float4*)mean;
    const float4* xv = (const float4*)xin;

    for (int t = tid; t < 64 * 32; t += 256) {
        int node = node0 + (t >> 5);
        float4 z = make_float4(0.f, 0.f, 0.f, 0.f);
        if (node < NN) {
            sm[t] = mv[node * 32 + (t & 31)];
            sx[t] = xv[node * 32 + (t & 31)];
        } else {
            sm[t] = z;
            sx[t] = z;
        }
    }
    __syncthreads();

    int tx = tid & 31;
    int ty = tid >> 5;
    int rbase = ty * 8;

    unsigned long long axy[8], azw[8];
#pragma unroll
    for (int i = 0; i < 8; i++) { axy[i] = 0ull; azw[i] = 0ull; }

    const float4* Wlv = (const float4*)Wl;   // [k][32 float4]
    const float4* Wrv = (const float4*)Wr;

    for (int k4 = 0; k4 < 32; k4++) {
        {
            float4 w0 = Wlv[(k4 * 4 + 0) * 32 + tx];
            float4 w1 = Wlv[(k4 * 4 + 1) * 32 + tx];
            float4 w2 = Wlv[(k4 * 4 + 2) * 32 + tx];
            float4 w3 = Wlv[(k4 * 4 + 3) * 32 + tx];
            unsigned long long w0xy = pk2(w0.x, w0.y), w0zw = pk2(w0.z, w0.w);
            unsigned long long w1xy = pk2(w1.x, w1.y), w1zw = pk2(w1.z, w1.w);
            unsigned long long w2xy = pk2(w2.x, w2.y), w2zw = pk2(w2.z, w2.w);
            unsigned long long w3xy = pk2(w3.x, w3.y), w3zw = pk2(w3.z, w3.w);
#pragma unroll
            for (int i = 0; i < 8; i++) {
                float4 m = sm[(rbase + i) * 32 + k4];
                unsigned long long mm;
                mm = pk2(m.x, m.x); ffma2(axy[i], mm, w0xy); ffma2(azw[i], mm, w0zw);
                mm = pk2(m.y, m.y); ffma2(axy[i], mm, w1xy); ffma2(azw[i], mm, w1zw);
                mm = pk2(m.z, m.z); ffma2(axy[i], mm, w2xy); ffma2(azw[i], mm, w2zw);
                mm = pk2(m.w, m.w); ffma2(axy[i], mm, w3xy); ffma2(azw[i], mm, w3zw);
            }
        }
        {
            float4 w0 = Wrv[(k4 * 4 + 0) * 32 + tx];
            float4 w1 = Wrv[(k4 * 4 + 1) * 32 + tx];
            float4 w2 = Wrv[(k4 * 4 + 2) * 32 + tx];
            float4 w3 = Wrv[(k4 * 4 + 3) * 32 + tx];
            unsigned long long w0xy = pk2(w0.x, w0.y), w0zw = pk2(w0.z, w0.w);
            unsigned long long w1xy = pk2(w1.x, w1.y), w1zw = pk2(w1.z, w1.w);
            unsigned long long w2xy = pk2(w2.x, w2.y), w2zw = pk2(w2.z, w2.w);
            unsigned long long w3xy = pk2(w3.x, w3.y), w3zw = pk2(w3.z, w3.w);
#pragma unroll
            for (int i = 0; i < 8; i++) {
                float4 m = sx[(rbase + i) * 32 + k4];
                unsigned long long mm;
                mm = pk2(m.x, m.x); ffma2(axy[i], mm, w0xy); ffma2(azw[i], mm, w0zw);
                mm = pk2(m.y, m.y); ffma2(axy[i], mm, w1xy); ffma2(azw[i], mm, w1zw);
                mm = pk2(m.z, m.z); ffma2(axy[i], mm, w2xy); ffma2(azw[i], mm, w2zw);
                mm = pk2(m.w, m.w); ffma2(axy[i], mm, w3xy); ffma2(azw[i], mm, w3zw);
            }
        }
    }

    float4 bb = ((const float4*)bias)[tx];
#pragma unroll
    for (int i = 0; i < 8; i++) {
        int node = node0 + rbase + i;
        if (node < NN) {
            float4 r;
            upk2(axy[i], r.x, r.y);
            upk2(azw[i], r.z, r.w);
            r.x += bb.x; r.y += bb.y; r.z += bb.z; r.w += bb.w;
            if (doRelu) {
                r.x = fmaxf(r.x, 0.f);
                r.y = fmaxf(r.y, 0.f);
                r.z = fmaxf(r.z, 0.f);
                r.w = fmaxf(r.w, 0.f);
            }
            ((float4*)outp)[node * 32 + tx] = r;
            if (outh) {
                __half2 a = __floats2half2_rn(r.x, r.y);
                __half2 b = __floats2half2_rn(r.z, r.w);
                uint2 u;
                u.x = *reinterpret_cast<unsigned*>(&a);
                u.y = *reinterpret_cast<unsigned*>(&b);
                ((uint2*)outh)[node * 32 + tx] = u;
            }
        }
    }
}

// ---------------- launch ----------------
extern "C" void kernel_launch(void* const* d_in, const int* in_sizes, int n_in,
                              void* d_out, int out_size) {
    const float* x   = (const float*)d_in[0];
    const void*  ei  = d_in[1];
    const float* Wl1 = (const float*)d_in[2];
    const float* Wr1 = (const float*)d_in[3];
    const float* b1  = (const float*)d_in[4];
    const float* Wl2 = (const float*)d_in[5];
    const float* Wr2 = (const float*)d_in[6];
    const float* b2  = (const float*)d_in[7];
    float* out = (float*)d_out;

    cudaFuncSetAttribute(k_linear, cudaFuncAttributeMaxDynamicSharedMemorySize,
                         65536);

    void *p_mean = nullptr, *p_h = nullptr, *p_xh = nullptr, *p_hh = nullptr;
    cudaGetSymbolAddress(&p_mean, g_mean);
    cudaGetSymbolAddress(&p_h, g_h);
    cudaGetSymbolAddress(&p_xh, g_xh);
    cudaGetSymbolAddress(&p_hh, g_hh);
    float*  mean = (float*)p_mean;
    float*  h    = (float*)p_h;
    __half* xh   = (__half*)p_xh;
    __half* hh   = (__half*)p_hh;

    // CSR build + fp16 cache of x
    k_detect<<<1, 32>>>(ei);
    k_zero_deg<<<(NN + 255) / 256, 256>>>();
    k_degree<<<(NE + 255) / 256, 256>>>(ei);
    k_tohalf<<<(NN * DD / 4 + 255) / 256, 256>>>(x, xh);
    k_scan1<<<NBLK, 256>>>();
    k_scan2<<<1, 512>>>();
    k_scan3<<<(NN + 255) / 256, 256>>>();
    k_fill<<<(NE + 255) / 256, 256>>>(ei);

    // Layer 1 (linear also emits fp16 h for layer-2 gather)
    k_agg<<<(NN + 7) / 8, 256>>>(xh, mean);
    k_linear<<<(NN + 63) / 64, 256, 65536>>>(mean, x, Wl1, Wr1, b1, h, hh, 1);

    // Layer 2
    k_agg<<<(NN + 7) / 8, 256>>>(hh, mean);
    k_linear<<<(NN + 63) / 64, 256, 65536>>>(mean, h, Wl2, Wr2, b2, out,
                                             (__half*)nullptr, 0);
}

// round 8
// speedup vs baseline: 2.2942x; 1.6086x over previous
#include <cuda_runtime.h>
#include <cuda_fp16.h>
#include <cstdint>

#define NN 100000
#define NE 1600000
#define DD 128
#define NBLK 391      // ceil(NN/256)
#define NTILE 782     // ceil(NN/128)

// SMEM padded row: 256 halves + 8 pad = 264 halves = 528 bytes (33 x 16B)
#define ROWB 528
#define SMEM_TOT (2 * 128 * ROWB)   // 135168

// ---------------- scratch (static __device__, allocation-free) ----------------
__device__ int    g_is64;
__device__ int    g_deg[NN];
__device__ int    g_local[NN];
__device__ int    g_bsum[NBLK];
__device__ int    g_boff[NBLK];
__device__ int    g_rowptr[NN + 1];
__device__ int    g_cursor[NN];
__device__ int    g_src[NE];
__device__ __half g_xh[(size_t)NN * DD];        // fp16 x cache
__device__ __half g_hh[(size_t)NN * DD];        // fp16 h cache
__device__ __half g_meanh[(size_t)NN * DD];     // fp16 mean
__device__ __half g_Bw0[128 * 256];             // [n][k] fp16: [Wl1;Wr1]
__device__ __half g_Bw1[128 * 256];             // [n][k] fp16: [Wl2;Wr2]

// ---------------- helpers ----------------------------------------------------
__device__ __forceinline__ uint32_t smem_u32(const void* p) {
    uint32_t a;
    asm("{ .reg .u64 t; cvta.to.shared.u64 t, %1; cvt.u32.u64 %0, t; }"
        : "=r"(a) : "l"(p));
    return a;
}
__device__ __forceinline__ void ldmx4(uint32_t& r0, uint32_t& r1,
                                      uint32_t& r2, uint32_t& r3, uint32_t a) {
    asm volatile("ldmatrix.sync.aligned.m8n8.x4.shared.b16 {%0,%1,%2,%3}, [%4];"
                 : "=r"(r0), "=r"(r1), "=r"(r2), "=r"(r3) : "r"(a));
}
__device__ __forceinline__ void mma16816(float* c, uint32_t a0, uint32_t a1,
                                         uint32_t a2, uint32_t a3,
                                         uint32_t b0, uint32_t b1) {
    asm volatile(
        "mma.sync.aligned.m16n8k16.row.col.f32.f16.f16.f32 "
        "{%0,%1,%2,%3}, {%4,%5,%6,%7}, {%8,%9}, {%0,%1,%2,%3};"
        : "+f"(c[0]), "+f"(c[1]), "+f"(c[2]), "+f"(c[3])
        : "r"(a0), "r"(a1), "r"(a2), "r"(a3), "r"(b0), "r"(b1));
}

// ---------------- dtype detection (int64 vs silently-int32 edge_index) -------
__global__ void k_detect(const void* ei) {
    int t = threadIdx.x;
    long long v = ((const long long*)ei)[t];
    unsigned bad = __ballot_sync(0xFFFFFFFFu, (v < 0) || (v >= NN));
    if (t == 0) g_is64 = (bad == 0) ? 1 : 0;
}
__device__ __forceinline__ int edge_src(const void* ei, int e) {
    return g_is64 ? (int)((const long long*)ei)[e] : ((const int*)ei)[e];
}
__device__ __forceinline__ int edge_dst(const void* ei, int e) {
    return g_is64 ? (int)((const long long*)ei)[(size_t)NE + e]
                  : ((const int*)ei)[(size_t)NE + e];
}

// ---------------- fp32 -> fp16 x cache ---------------------------------------
__global__ void __launch_bounds__(256) k_tohalf(const float* __restrict__ in,
                                                __half* __restrict__ outp) {
    int i = blockIdx.x * blockDim.x + threadIdx.x;
    if (i >= NN * DD / 4) return;
    float4 v = ((const float4*)in)[i];
    __half2 a = __floats2half2_rn(v.x, v.y);
    __half2 b = __floats2half2_rn(v.z, v.w);
    uint2 u;
    u.x = *reinterpret_cast<unsigned*>(&a);
    u.y = *reinterpret_cast<unsigned*>(&b);
    ((uint2*)outp)[i] = u;
}

// ---------------- weight prep: fp16 B[n][k] = [Wl;Wr] transposed -------------
__global__ void __launch_bounds__(256) k_prepB(const float* __restrict__ Wl1,
                                               const float* __restrict__ Wr1,
                                               const float* __restrict__ Wl2,
                                               const float* __restrict__ Wr2) {
    int idx = blockIdx.x * blockDim.x + threadIdx.x;   // 65536 total
    if (idx >= 2 * 128 * 256) return;
    int layer = idx >> 15;
    int rem = idx & 32767;
    int n = rem >> 8;
    int k = rem & 255;
    const float* Wl = layer ? Wl2 : Wl1;
    const float* Wr = layer ? Wr2 : Wr1;
    float v = (k < 128) ? Wl[k * 128 + n] : Wr[(k - 128) * 128 + n];
    (layer ? g_Bw1 : g_Bw0)[n * 256 + k] = __float2half_rn(v);
}

// ---------------- CSR build ----------------
__global__ void k_zero_deg() {
    int i = blockIdx.x * blockDim.x + threadIdx.x;
    if (i < NN) g_deg[i] = 0;
}
__global__ void k_degree(const void* ei) {
    int e = blockIdx.x * blockDim.x + threadIdx.x;
    if (e >= NE) return;
    atomicAdd(&g_deg[edge_dst(ei, e)], 1);
}
__global__ void __launch_bounds__(256) k_scan1() {
    __shared__ int ws[8];
    int b = blockIdx.x, t = threadIdx.x;
    int i = b * 256 + t;
    int v = (i < NN) ? g_deg[i] : 0;
    int x = v;
#pragma unroll
    for (int o = 1; o < 32; o <<= 1) {
        int y = __shfl_up_sync(0xFFFFFFFFu, x, o);
        if ((t & 31) >= o) x += y;
    }
    if ((t & 31) == 31) ws[t >> 5] = x;
    __syncthreads();
    if (t < 8) {
        int y = ws[t];
#pragma unroll
        for (int o = 1; o < 8; o <<= 1) {
            int z = __shfl_up_sync(0x000000FFu, y, o);
            if (t >= o) y += z;
        }
        ws[t] = y;
    }
    __syncthreads();
    int incl = x + ((t >= 32) ? ws[(t >> 5) - 1] : 0);
    if (i < NN) g_local[i] = incl - v;
    if (t == 255) g_bsum[b] = incl;
}
__global__ void __launch_bounds__(512) k_scan2() {
    __shared__ int ws[16];
    int t = threadIdx.x;
    int v = (t < NBLK) ? g_bsum[t] : 0;
    int x = v;
#pragma unroll
    for (int o = 1; o < 32; o <<= 1) {
        int y = __shfl_up_sync(0xFFFFFFFFu, x, o);
        if ((t & 31) >= o) x += y;
    }
    if ((t & 31) == 31) ws[t >> 5] = x;
    __syncthreads();
    if (t < 16) {
        int y = ws[t];
#pragma unroll
        for (int o = 1; o < 16; o <<= 1) {
            int z = __shfl_up_sync(0x0000FFFFu, y, o);
            if (t >= o) y += z;
        }
        ws[t] = y;
    }
    __syncthreads();
    int incl = x + ((t >= 32) ? ws[(t >> 5) - 1] : 0);
    if (t < NBLK) g_boff[t] = incl - v;
    if (t == NBLK - 1) g_rowptr[NN] = incl;
}
__global__ void k_scan3() {
    int i = blockIdx.x * blockDim.x + threadIdx.x;
    if (i >= NN) return;
    int r = g_boff[i >> 8] + g_local[i];
    g_rowptr[i] = r;
    g_cursor[i] = r;
}
__global__ void k_fill(const void* ei) {
    int e = blockIdx.x * blockDim.x + threadIdx.x;
    if (e >= NE) return;
    int s = edge_src(ei, e);
    int d = edge_dst(ei, e);
    int pos = atomicAdd(&g_cursor[d], 1);
    g_src[pos] = s;
}

// ---------------- mean aggregation: fp16 in, fp32 accum, fp16 out ------------
__global__ void __launch_bounds__(256) k_aggh(const __half* __restrict__ in,
                                              __half* __restrict__ outp) {
    int warp = (blockIdx.x * blockDim.x + threadIdx.x) >> 5;
    int lane = threadIdx.x & 31;
    if (warp >= NN) return;
    int beg = g_rowptr[warp];
    int end = g_rowptr[warp + 1];
    const uint2* iv = (const uint2*)in;
    float4 acc0 = make_float4(0.f, 0.f, 0.f, 0.f);
    float4 acc1 = make_float4(0.f, 0.f, 0.f, 0.f);
    int e = beg;
    for (; e + 8 <= end; e += 8) {
        int s0 = g_src[e],     s1 = g_src[e + 1], s2 = g_src[e + 2], s3 = g_src[e + 3];
        int s4 = g_src[e + 4], s5 = g_src[e + 5], s6 = g_src[e + 6], s7 = g_src[e + 7];
        uint2 u0 = iv[s0 * 32 + lane];
        uint2 u1 = iv[s1 * 32 + lane];
        uint2 u2 = iv[s2 * 32 + lane];
        uint2 u3 = iv[s3 * 32 + lane];
        uint2 u4 = iv[s4 * 32 + lane];
        uint2 u5 = iv[s5 * 32 + lane];
        uint2 u6 = iv[s6 * 32 + lane];
        uint2 u7 = iv[s7 * 32 + lane];
#define ACCUM(ACC, U)                                                         \
        {                                                                     \
            float2 lo = __half22float2(*reinterpret_cast<__half2*>(&(U).x));  \
            float2 hi = __half22float2(*reinterpret_cast<__half2*>(&(U).y));  \
            ACC.x += lo.x; ACC.y += lo.y; ACC.z += hi.x; ACC.w += hi.y;       \
        }
        ACCUM(acc0, u0) ACCUM(acc0, u1) ACCUM(acc0, u2) ACCUM(acc0, u3)
        ACCUM(acc1, u4) ACCUM(acc1, u5) ACCUM(acc1, u6) ACCUM(acc1, u7)
    }
    for (; e < end; e++) {
        uint2 u = iv[g_src[e] * 32 + lane];
        ACCUM(acc0, u)
    }
#undef ACCUM
    int deg = end - beg;
    float inv = 1.0f / (float)(deg > 0 ? deg : 1);
    __half2 a = __floats2half2_rn((acc0.x + acc1.x) * inv, (acc0.y + acc1.y) * inv);
    __half2 b = __floats2half2_rn((acc0.z + acc1.z) * inv, (acc0.w + acc1.w) * inv);
    uint2 u;
    u.x = *reinterpret_cast<unsigned*>(&a);
    u.y = *reinterpret_cast<unsigned*>(&b);
    ((uint2*)outp)[warp * 32 + lane] = u;
}

// ---------------- HMMA fused dual-GEMM ---------------------------------------
// Per CTA: 128-node tile. A = [mean | x] fp16 (128 x 256), B = [Wl;Wr] fp16
// (128 x 256, [n][k]). 8 warps = 8 m16 tiles; per warp 16 n8 tiles, 16 k16
// steps of mma.sync.m16n8k16 f32 accum. Rows padded to 528B in SMEM ->
// conflict-free ldmatrix.
__global__ void __launch_bounds__(256) k_gemm(const __half* __restrict__ Am,
                                              const __half* __restrict__ Ax,
                                              const __half* __restrict__ Bw,
                                              const float* __restrict__ bias,
                                              float* __restrict__ outp,
                                              __half* __restrict__ outh,
                                              int doRelu) {
    extern __shared__ char smem[];
    char* As = smem;                         // 128 rows x 528B
    char* Bs = smem + 128 * ROWB;            // 128 rows x 528B
    int tid = threadIdx.x;
    int wid = tid >> 5, lane = tid & 31;
    int node0 = blockIdx.x * 128;

    // Stage B (weights): row n, 32 x 16B chunks.
    {
        const uint4* bsrc = (const uint4*)Bw;
        for (int t = tid; t < 4096; t += 256) {
            int row = t >> 5, c = t & 31;
            *(uint4*)(Bs + row * ROWB + c * 16) = bsrc[row * 32 + c];
        }
    }
    // Stage A: [mean | x] per node row.
    for (int t = tid; t < 4096; t += 256) {
        int row = t >> 5, c = t & 31;
        int node = node0 + row;
        uint4 v = make_uint4(0, 0, 0, 0);
        if (node < NN) {
            v = (c < 16)
                ? ((const uint4*)(Am + (size_t)node * 128))[c]
                : ((const uint4*)(Ax + (size_t)node * 128))[c - 16];
        }
        *(uint4*)(As + row * ROWB + c * 16) = v;
    }
    __syncthreads();

    int m0 = wid * 16;
    // A ldmatrix lane address: row m0+(lane&15), k-offset (lane>>4)*8
    uint32_t aaddr = smem_u32(As) + (m0 + (lane & 15)) * ROWB + ((lane >> 4) * 8) * 2;
    // B ldmatrix lane address (pair of n8 tiles): n = (lane&7)+(lane>>4)*8,
    // k-offset ((lane>>3)&1)*8
    uint32_t baddr = smem_u32(Bs) + ((lane & 7) + ((lane >> 4) << 3)) * ROWB +
                     (((lane >> 3) & 1) * 8) * 2;

    float c[16][4];
#pragma unroll
    for (int i = 0; i < 16; i++)
#pragma unroll
        for (int j = 0; j < 4; j++) c[i][j] = 0.f;

#pragma unroll
    for (int k0 = 0; k0 < 256; k0 += 16) {
        uint32_t a0, a1, a2, a3;
        ldmx4(a0, a1, a2, a3, aaddr + k0 * 2);
#pragma unroll
        for (int p = 0; p < 8; p++) {
            uint32_t b0, b1, b2, b3;
            ldmx4(b0, b1, b2, b3, baddr + p * 16 * ROWB + k0 * 2);
            mma16816(c[2 * p],     a0, a1, a2, a3, b0, b1);
            mma16816(c[2 * p + 1], a0, a1, a2, a3, b2, b3);
        }
    }

    // Epilogue: c[nt] -> rows (m0+gID, m0+gID+8), cols nt*8 + 2*tig (+1)
    int gID = lane >> 2, tig = lane & 3;
    int nodeA = node0 + m0 + gID;
    int nodeB = nodeA + 8;
#pragma unroll
    for (int nt = 0; nt < 16; nt++) {
        int col = nt * 8 + 2 * tig;
        float2 bb = *(const float2*)(bias + col);
        float v0 = c[nt][0] + bb.x, v1 = c[nt][1] + bb.y;
        float v2 = c[nt][2] + bb.x, v3 = c[nt][3] + bb.y;
        if (doRelu) {
            v0 = fmaxf(v0, 0.f); v1 = fmaxf(v1, 0.f);
            v2 = fmaxf(v2, 0.f); v3 = fmaxf(v3, 0.f);
        }
        if (nodeA < NN) {
            if (outp) ((float2*)outp)[(size_t)nodeA * 64 + nt * 4 + tig] =
                make_float2(v0, v1);
            if (outh) {
                __half2 hh = __floats2half2_rn(v0, v1);
                ((__half2*)outh)[(size_t)nodeA * 64 + nt * 4 + tig] = hh;
            }
        }
        if (nodeB < NN) {
            if (outp) ((float2*)outp)[(size_t)nodeB * 64 + nt * 4 + tig] =
                make_float2(v2, v3);
            if (outh) {
                __half2 hh = __floats2half2_rn(v2, v3);
                ((__half2*)outh)[(size_t)nodeB * 64 + nt * 4 + tig] = hh;
            }
        }
    }
}

// ---------------- launch ----------------
extern "C" void kernel_launch(void* const* d_in, const int* in_sizes, int n_in,
                              void* d_out, int out_size) {
    const float* x   = (const float*)d_in[0];
    const void*  ei  = d_in[1];
    const float* Wl1 = (const float*)d_in[2];
    const float* Wr1 = (const float*)d_in[3];
    const float* b1  = (const float*)d_in[4];
    const float* Wl2 = (const float*)d_in[5];
    const float* Wr2 = (const float*)d_in[6];
    const float* b2  = (const float*)d_in[7];
    float* out = (float*)d_out;

    cudaFuncSetAttribute(k_gemm, cudaFuncAttributeMaxDynamicSharedMemorySize,
                         SMEM_TOT);

    void *p_xh, *p_hh, *p_mh, *p_b0, *p_b1;
    cudaGetSymbolAddress(&p_xh, g_xh);
    cudaGetSymbolAddress(&p_hh, g_hh);
    cudaGetSymbolAddress(&p_mh, g_meanh);
    cudaGetSymbolAddress(&p_b0, g_Bw0);
    cudaGetSymbolAddress(&p_b1, g_Bw1);
    __half* xh = (__half*)p_xh;
    __half* hh = (__half*)p_hh;
    __half* mh = (__half*)p_mh;
    __half* B0 = (__half*)p_b0;
    __half* B1 = (__half*)p_b1;

    // CSR build + fp16 caches + weight prep
    k_detect<<<1, 32>>>(ei);
    k_zero_deg<<<(NN + 255) / 256, 256>>>();
    k_tohalf<<<(NN * DD / 4 + 255) / 256, 256>>>(x, xh);
    k_degree<<<(NE + 255) / 256, 256>>>(ei);
    k_prepB<<<256, 256>>>(Wl1, Wr1, Wl2, Wr2);
    k_scan1<<<NBLK, 256>>>();
    k_scan2<<<1, 512>>>();
    k_scan3<<<(NN + 255) / 256, 256>>>();
    k_fill<<<(NE + 255) / 256, 256>>>(ei);

    // Layer 1: agg(xh) -> meanh; GEMM -> hh (fp16, relu)
    k_aggh<<<(NN + 7) / 8, 256>>>(xh, mh);
    k_gemm<<<NTILE, 256, SMEM_TOT>>>(mh, xh, B0, b1, (float*)nullptr, hh, 1);

    // Layer 2: agg(hh) -> meanh; GEMM -> d_out (fp32)
    k_aggh<<<(NN + 7) / 8, 256>>>(hh, mh);
    k_gemm<<<NTILE, 256, SMEM_TOT>>>(mh, hh, B1, b2, out, (__half*)nullptr, 0);
}